// round 1
// baseline (speedup 1.0000x reference)
#include <cuda_runtime.h>
#include <cuda_bf16.h>
#include <math.h>

// Problem constants
#define EMBD   256
#define HEADS  16
#define DHEAD  16
#define BATCH  64
#define MROWS  128
#define JJOBS  512
#define TTOK   513            // J + 1 (skip token prepended)
#define OUT_PER_B (MROWS * TTOK)   // 65664

// -------- scratch (static device memory; no allocations allowed) --------
__device__ float g_Q [BATCH * MROWS * EMBD];   // (B*128, 256)
__device__ float g_K [BATCH * TTOK  * EMBD];   // (B*513, 256)
__device__ float g_V [BATCH * TTOK  * EMBD];   // (B*513, 256)
__device__ float g_O [BATCH * MROWS * EMBD];   // attention out concat
__device__ float g_MH[BATCH * MROWS * EMBD];   // mh = O @ Wc + bc
__device__ float g_SUM[BATCH];                 // per-batch softmax denominators

// row pointer into the virtual "jobs" tensor (skip token at t==0)
__device__ __forceinline__ const float* jobs_row(const float* __restrict__ jobs,
                                                 const float* __restrict__ skip,
                                                 int b, int t) {
    return (t == 0) ? skip : jobs + ((long)b * JJOBS + (t - 1)) * EMBD;
}

__global__ void zero_sums_kernel(float* __restrict__ sums) {
    sums[threadIdx.x] = 0.0f;
}

// ======================= generic 256-K SGEMM =======================
// C (rows x 256) = X (rows x 256) @ W (256 x 256) [+ bias]
// MODE 0: X direct rows, no bias
// MODE 1: X is the virtual jobs tensor (row = b*513 + t), no bias
// MODE 2: X direct rows, add bias
// Tiles: BM=64, BN=64, BK=16; 256 threads; 4x4 outputs per thread.
#define GBM 64
#define GBN 64
#define GBK 16
#define APAD 4   // As stride = 68 (16B-aligned float4 reads)

template <int MODE>
__global__ void __launch_bounds__(256)
gemm256_kernel(const float* __restrict__ X, const float* __restrict__ skip,
               const float* __restrict__ W, const float* __restrict__ bias,
               float* __restrict__ C)
{
    __shared__ float As[GBK][GBM + APAD];
    __shared__ float Bs[GBK][GBN];

    const int tid  = threadIdx.x;
    const int row0 = blockIdx.y * GBM;
    const int col0 = blockIdx.x * GBN;

    // A-load mapping: one float4 along K per thread
    const int a_row = tid >> 2;          // 0..63
    const int a_kc  = (tid & 3) * 4;     // 0,4,8,12
    // B-load mapping: one float4 along N per thread
    const int b_k   = tid >> 4;          // 0..15
    const int b_nc  = (tid & 15) * 4;    // 0..60

    const int tx = tid & 15;             // output col group
    const int ty = tid >> 4;             // output row group

    // resolve the A row pointer once (independent of k0)
    const float* xrow;
    {
        const int grow = row0 + a_row;
        if (MODE == 1) {
            const int b = grow / TTOK;
            const int t = grow - b * TTOK;
            xrow = jobs_row(X, skip, b, t);
        } else {
            xrow = X + (long)grow * EMBD;
        }
    }

    float acc[4][4] = {};

    for (int k0 = 0; k0 < EMBD; k0 += GBK) {
        // load A tile (transposed into smem)
        float4 av = *(const float4*)(xrow + k0 + a_kc);
        As[a_kc + 0][a_row] = av.x;
        As[a_kc + 1][a_row] = av.y;
        As[a_kc + 2][a_row] = av.z;
        As[a_kc + 3][a_row] = av.w;
        // load B tile
        *(float4*)&Bs[b_k][b_nc] =
            *(const float4*)(W + (long)(k0 + b_k) * EMBD + col0 + b_nc);
        __syncthreads();

        #pragma unroll
        for (int kk = 0; kk < GBK; kk++) {
            float4 a4 = *(const float4*)&As[kk][ty * 4];
            float4 b4 = *(const float4*)&Bs[kk][tx * 4];
            float a[4] = {a4.x, a4.y, a4.z, a4.w};
            float b[4] = {b4.x, b4.y, b4.z, b4.w};
            #pragma unroll
            for (int i = 0; i < 4; i++)
                #pragma unroll
                for (int j = 0; j < 4; j++)
                    acc[i][j] = fmaf(a[i], b[j], acc[i][j]);
        }
        __syncthreads();
    }

    float4 bb = make_float4(0.f, 0.f, 0.f, 0.f);
    if (MODE == 2) bb = *(const float4*)(bias + col0 + tx * 4);

    #pragma unroll
    for (int i = 0; i < 4; i++) {
        const int r = row0 + ty * 4 + i;
        float4 o;
        o.x = acc[i][0] + bb.x;
        o.y = acc[i][1] + bb.y;
        o.z = acc[i][2] + bb.z;
        o.w = acc[i][3] + bb.w;
        *(float4*)(C + (long)r * EMBD + col0 + tx * 4) = o;
    }
}

// ======================= fused attention (D=16, online softmax) ===========
// grid (H=16, B=64), block 128 (one thread per query row m)
__global__ void __launch_bounds__(128)
attn_kernel(const float* __restrict__ Q, const float* __restrict__ K,
            const float* __restrict__ V, float* __restrict__ O)
{
    constexpr int CH = 128;
    __shared__ float Ks[CH][DHEAD];
    __shared__ float Vs[CH][DHEAD];

    const int h = blockIdx.x;
    const int b = blockIdx.y;
    const int m = threadIdx.x;

    float q[DHEAD];
    {
        const float* qp = Q + ((long)b * MROWS + m) * EMBD + h * DHEAD;
        #pragma unroll
        for (int i = 0; i < 4; i++) {
            float4 v4 = *(const float4*)(qp + i * 4);
            q[i*4+0] = v4.x; q[i*4+1] = v4.y; q[i*4+2] = v4.z; q[i*4+3] = v4.w;
        }
    }

    float mrun = -1e30f, l = 0.0f;
    float acc[DHEAD] = {};

    for (int t0 = 0; t0 < TTOK; t0 += CH) {
        const int cnt = min(CH, TTOK - t0);
        __syncthreads();
        for (int j = threadIdx.x; j < cnt * 4; j += 128) {
            const int r = j >> 2, c = (j & 3) * 4;
            const long base = ((long)b * TTOK + t0 + r) * EMBD + h * DHEAD + c;
            *(float4*)&Ks[r][c] = *(const float4*)(K + base);
            *(float4*)&Vs[r][c] = *(const float4*)(V + base);
        }
        __syncthreads();

        for (int t = 0; t < cnt; t++) {
            float s = 0.0f;
            #pragma unroll
            for (int i = 0; i < DHEAD; i++) s = fmaf(q[i], Ks[t][i], s);
            s *= 0.25f;  // 1/SQRT_QKV
            const float mnew = fmaxf(mrun, s);
            const float corr = __expf(mrun - mnew);
            const float p    = __expf(s - mnew);
            l = l * corr + p;
            #pragma unroll
            for (int i = 0; i < DHEAD; i++)
                acc[i] = fmaf(acc[i], corr, p * Vs[t][i]);
            mrun = mnew;
        }
    }

    const float inv = 1.0f / l;
    float* op = O + ((long)b * MROWS + m) * EMBD + h * DHEAD;
    #pragma unroll
    for (int i = 0; i < 4; i++) {
        float4 o;
        o.x = acc[i*4+0] * inv; o.y = acc[i*4+1] * inv;
        o.z = acc[i*4+2] * inv; o.w = acc[i*4+3] * inv;
        *(float4*)(op + i * 4) = o;
    }
}

// ======================= score2 GEMM + tanh/exp epilogue ===================
// Per batch b: L(m,t) = exp( 10*tanh( (mh[b] @ jobs[b]^T)/16 ) + mask )
// writes exp-logits to d_out and accumulates per-batch sums (atomic).
// Logits are bounded by |10 + mask| so no max-subtraction is needed.
// grid (tblocks=9, mblocks=2, B=64); block 256.
__global__ void __launch_bounds__(256)
score2_kernel(const float* __restrict__ MH, const float* __restrict__ jobs,
              const float* __restrict__ skip, const float* __restrict__ mask,
              float* __restrict__ out, float* __restrict__ sums)
{
    __shared__ float As[GBK][GBM + APAD];
    __shared__ float Bs[GBK][GBN + APAD];
    __shared__ float red[256];

    const int tid  = threadIdx.x;
    const int b    = blockIdx.z;
    const int row0 = blockIdx.y * GBM;   // m offset
    const int col0 = blockIdx.x * GBN;   // t offset

    const int a_row = tid >> 2;
    const int a_kc  = (tid & 3) * 4;
    const int tx = tid & 15;
    const int ty = tid >> 4;

    const float* arow = MH + ((long)b * MROWS + row0 + a_row) * EMBD;

    // B row pointer: column t of the tile (transposed load)
    const int t_l = tid >> 2;                  // 0..63 (tile-local t)
    const int t_g = col0 + t_l;
    const float* brow = (t_g < TTOK) ? jobs_row(jobs, skip, b, t_g) : nullptr;

    float acc[4][4] = {};

    for (int k0 = 0; k0 < EMBD; k0 += GBK) {
        float4 av = *(const float4*)(arow + k0 + a_kc);
        As[a_kc + 0][a_row] = av.x;
        As[a_kc + 1][a_row] = av.y;
        As[a_kc + 2][a_row] = av.z;
        As[a_kc + 3][a_row] = av.w;

        float4 bv = make_float4(0.f, 0.f, 0.f, 0.f);
        if (brow) bv = *(const float4*)(brow + k0 + a_kc);
        Bs[a_kc + 0][t_l] = bv.x;
        Bs[a_kc + 1][t_l] = bv.y;
        Bs[a_kc + 2][t_l] = bv.z;
        Bs[a_kc + 3][t_l] = bv.w;
        __syncthreads();

        #pragma unroll
        for (int kk = 0; kk < GBK; kk++) {
            float4 a4 = *(const float4*)&As[kk][ty * 4];
            float4 b4 = *(const float4*)&Bs[kk][tx * 4];
            float a[4] = {a4.x, a4.y, a4.z, a4.w};
            float bb[4] = {b4.x, b4.y, b4.z, b4.w};
            #pragma unroll
            for (int i = 0; i < 4; i++)
                #pragma unroll
                for (int j = 0; j < 4; j++)
                    acc[i][j] = fmaf(a[i], bb[j], acc[i][j]);
        }
        __syncthreads();
    }

    float lsum = 0.0f;
    #pragma unroll
    for (int i = 0; i < 4; i++) {
        const int m = row0 + ty * 4 + i;
        #pragma unroll
        for (int j = 0; j < 4; j++) {
            const int t = col0 + tx * 4 + j;
            if (t < TTOK) {
                const float s  = acc[i][j] * 0.0625f;   // 1/SQRT_EMB
                const long  li = (long)b * OUT_PER_B + (long)m * TTOK + t;
                const float lg = 10.0f * tanhf(s) + mask[li];
                const float y  = __expf(lg);
                out[li] = y;
                lsum += y;
            }
        }
    }

    // block reduce + one atomic per block
    red[tid] = lsum;
    __syncthreads();
    #pragma unroll
    for (int s = 128; s > 0; s >>= 1) {
        if (tid < s) red[tid] += red[tid + s];
        __syncthreads();
    }
    if (tid == 0) atomicAdd(&sums[b], red[0]);
}

// ======================= normalize =======================
__global__ void __launch_bounds__(256)
norm_kernel(float* __restrict__ out, const float* __restrict__ sums, long n)
{
    long i = (long)blockIdx.x * blockDim.x + threadIdx.x;
    const long stride = (long)gridDim.x * blockDim.x;
    for (; i < n; i += stride) {
        const int b = (int)(i / OUT_PER_B);
        out[i] = out[i] / sums[b];
    }
}

// ======================= launch =======================
extern "C" void kernel_launch(void* const* d_in, const int* in_sizes, int n_in,
                              void* d_out, int out_size)
{
    const float* machine = (const float*)d_in[0];  // (64,128,256)
    const float* jobs    = (const float*)d_in[1];  // (64,512,256)
    const float* mask    = (const float*)d_in[2];  // (64,128,513)
    const float* Wq3     = (const float*)d_in[3];  // (256,256)
    const float* Wk      = (const float*)d_in[4];
    const float* Wv      = (const float*)d_in[5];
    const float* Wc      = (const float*)d_in[6];
    const float* bc      = (const float*)d_in[7];  // (256,)
    const float* skip    = (const float*)d_in[8];  // (1,1,256)
    float* out = (float*)d_out;

    float *Qp, *Kp, *Vp, *Op, *MHp, *Sp;
    cudaGetSymbolAddress((void**)&Qp,  g_Q);
    cudaGetSymbolAddress((void**)&Kp,  g_K);
    cudaGetSymbolAddress((void**)&Vp,  g_V);
    cudaGetSymbolAddress((void**)&Op,  g_O);
    cudaGetSymbolAddress((void**)&MHp, g_MH);
    cudaGetSymbolAddress((void**)&Sp,  g_SUM);

    zero_sums_kernel<<<1, BATCH>>>(Sp);

    // Q projection: 8192 rows
    gemm256_kernel<0><<<dim3(EMBD / GBN, (BATCH * MROWS) / GBM), 256>>>(
        machine, nullptr, Wq3, nullptr, Qp);
    // K, V projections over virtual jobs tensor: 32832 rows (513 tiles)
    gemm256_kernel<1><<<dim3(EMBD / GBN, (BATCH * TTOK) / GBM), 256>>>(
        jobs, skip, Wk, nullptr, Kp);
    gemm256_kernel<1><<<dim3(EMBD / GBN, (BATCH * TTOK) / GBM), 256>>>(
        jobs, skip, Wv, nullptr, Vp);

    // fused multi-head attention
    attn_kernel<<<dim3(HEADS, BATCH), 128>>>(Qp, Kp, Vp, Op);

    // output projection with bias
    gemm256_kernel<2><<<dim3(EMBD / GBN, (BATCH * MROWS) / GBM), 256>>>(
        Op, nullptr, Wc, bc, MHp);

    // score2 + tanh clip + exp + per-batch sum
    score2_kernel<<<dim3((TTOK + GBN - 1) / GBN, MROWS / GBM, BATCH), 256>>>(
        MHp, jobs, skip, mask, out, Sp);

    // normalize to probabilities
    const long n = (long)BATCH * OUT_PER_B;
    int blocks = (int)((n + 255) / 256);
    if (blocks > 16384) blocks = 16384;
    norm_kernel<<<blocks, 256>>>(out, Sp, n);
}

// round 2
// speedup vs baseline: 1.1076x; 1.1076x over previous
#include <cuda_runtime.h>
#include <cuda_bf16.h>
#include <math.h>

#define EMBD   256
#define HEADS  16
#define DHEAD  16
#define BATCH  64
#define MROWS  128
#define JJOBS  512
#define TTOK   513
#define OUT_PER_B (MROWS * TTOK)   // 65664

__device__ float g_Q [BATCH * MROWS * EMBD];
__device__ float g_K [BATCH * TTOK  * EMBD];
__device__ float g_V [BATCH * TTOK  * EMBD];
__device__ float g_O [BATCH * MROWS * EMBD];
__device__ float g_MH[BATCH * MROWS * EMBD];
__device__ float g_SUM[BATCH];

__device__ __forceinline__ const float* jobs_row(const float* __restrict__ jobs,
                                                 const float* __restrict__ skip,
                                                 int b, int t) {
    return (t == 0) ? skip : jobs + ((long)b * JJOBS + (t - 1)) * EMBD;
}

__global__ void zero_sums_kernel(float* __restrict__ sums) {
    sums[threadIdx.x] = 0.0f;
}

// =================== 128x128x16 SGEMM, 8x8 microtile, double buffered =====
// MODE 0: direct rows, no bias          (Q projection, etc.)
// MODE 1: virtual jobs rows, no bias, z-dim selects (W,C) pair  (K/V)
// MODE 2: direct rows, + bias           (Wc projection)
#define BM 128
#define BN 128
#define BK 16
#define ASTRIDE (BM + 4)

template <int MODE>
__global__ void __launch_bounds__(256, 2)
gemm128_kernel(const float* __restrict__ X, const float* __restrict__ skip,
               const float* __restrict__ Wa, const float* __restrict__ Wb,
               const float* __restrict__ bias,
               float* __restrict__ Ca, float* __restrict__ Cb, int nrows)
{
    __shared__ float As[2][BK][ASTRIDE];
    __shared__ float Bs[2][BK][BN];

    const float* W = (MODE == 1 && blockIdx.z == 1) ? Wb : Wa;
    float*       C = (MODE == 1 && blockIdx.z == 1) ? Cb : Ca;

    const int tid  = threadIdx.x;
    const int row0 = blockIdx.y * BM;
    const int col0 = blockIdx.x * BN;

    // A loader: row = tid>>1 (0..127), k-offset = (tid&1)*8 -> two float4
    const int a_row = tid >> 1;
    const int a_k   = (tid & 1) * 8;
    // B loader: k = tid>>4 (0..15), n = (tid&15)*8 -> two float4
    const int b_k   = tid >> 4;
    const int b_n   = (tid & 15) * 8;

    const int tx = tid & 15;   // col groups: tx*4 and 64+tx*4
    const int ty = tid >> 4;   // row groups: ty*4 and 64+ty*4

    // resolve A row pointer once
    const float* xrow;
    {
        int grow = row0 + a_row;
        if (grow > nrows - 1) grow = nrows - 1;
        if (MODE == 1) {
            const int b = grow / TTOK;
            const int t = grow - b * TTOK;
            xrow = jobs_row(X, skip, b, t);
        } else {
            xrow = X + (long)grow * EMBD;
        }
    }
    const float* wptr = W + (long)b_k * EMBD + col0 + b_n;

    float4 av0, av1, bv0, bv1;
    // prologue: load k0 = 0
    av0 = *(const float4*)(xrow + a_k);
    av1 = *(const float4*)(xrow + a_k + 4);
    bv0 = *(const float4*)(wptr);
    bv1 = *(const float4*)(wptr + 4);
    {
        As[0][a_k + 0][a_row] = av0.x; As[0][a_k + 1][a_row] = av0.y;
        As[0][a_k + 2][a_row] = av0.z; As[0][a_k + 3][a_row] = av0.w;
        As[0][a_k + 4][a_row] = av1.x; As[0][a_k + 5][a_row] = av1.y;
        As[0][a_k + 6][a_row] = av1.z; As[0][a_k + 7][a_row] = av1.w;
        *(float4*)&Bs[0][b_k][b_n]     = bv0;
        *(float4*)&Bs[0][b_k][b_n + 4] = bv1;
    }
    __syncthreads();

    float acc[8][8] = {};

    #pragma unroll 1
    for (int ks = 0; ks < EMBD / BK; ks++) {
        const int cur = ks & 1;
        const bool has_next = (ks < EMBD / BK - 1);
        if (has_next) {
            const int k0 = (ks + 1) * BK;
            av0 = *(const float4*)(xrow + k0 + a_k);
            av1 = *(const float4*)(xrow + k0 + a_k + 4);
            bv0 = *(const float4*)(wptr + (long)k0 * EMBD);
            bv1 = *(const float4*)(wptr + (long)k0 * EMBD + 4);
        }

        #pragma unroll
        for (int kk = 0; kk < BK; kk++) {
            float4 a0 = *(const float4*)&As[cur][kk][ty * 4];
            float4 a1 = *(const float4*)&As[cur][kk][64 + ty * 4];
            float4 b0 = *(const float4*)&Bs[cur][kk][tx * 4];
            float4 b1 = *(const float4*)&Bs[cur][kk][64 + tx * 4];
            float a[8] = {a0.x,a0.y,a0.z,a0.w,a1.x,a1.y,a1.z,a1.w};
            float b[8] = {b0.x,b0.y,b0.z,b0.w,b1.x,b1.y,b1.z,b1.w};
            #pragma unroll
            for (int i = 0; i < 8; i++)
                #pragma unroll
                for (int j = 0; j < 8; j++)
                    acc[i][j] = fmaf(a[i], b[j], acc[i][j]);
        }

        if (has_next) {
            const int nxt = 1 - cur;
            As[nxt][a_k + 0][a_row] = av0.x; As[nxt][a_k + 1][a_row] = av0.y;
            As[nxt][a_k + 2][a_row] = av0.z; As[nxt][a_k + 3][a_row] = av0.w;
            As[nxt][a_k + 4][a_row] = av1.x; As[nxt][a_k + 5][a_row] = av1.y;
            As[nxt][a_k + 6][a_row] = av1.z; As[nxt][a_k + 7][a_row] = av1.w;
            *(float4*)&Bs[nxt][b_k][b_n]     = bv0;
            *(float4*)&Bs[nxt][b_k][b_n + 4] = bv1;
        }
        __syncthreads();
    }

    float4 bb0 = make_float4(0.f,0.f,0.f,0.f), bb1 = bb0;
    if (MODE == 2) {
        bb0 = *(const float4*)(bias + col0 + tx * 4);
        bb1 = *(const float4*)(bias + col0 + 64 + tx * 4);
    }

    #pragma unroll
    for (int half = 0; half < 2; half++) {
        #pragma unroll
        for (int i = 0; i < 4; i++) {
            const int r = row0 + half * 64 + ty * 4 + i;
            if (r < nrows) {
                const int ai = half * 4 + i;
                float4 o0, o1;
                o0.x = acc[ai][0] + bb0.x; o0.y = acc[ai][1] + bb0.y;
                o0.z = acc[ai][2] + bb0.z; o0.w = acc[ai][3] + bb0.w;
                o1.x = acc[ai][4] + bb1.x; o1.y = acc[ai][5] + bb1.y;
                o1.z = acc[ai][6] + bb1.z; o1.w = acc[ai][7] + bb1.w;
                *(float4*)(C + (long)r * EMBD + col0 + tx * 4)      = o0;
                *(float4*)(C + (long)r * EMBD + col0 + 64 + tx * 4) = o1;
            }
        }
    }
}

// =================== fused attention, 16-token sub-chunks ==================
__global__ void __launch_bounds__(128)
attn_kernel(const float* __restrict__ Q, const float* __restrict__ K,
            const float* __restrict__ V, float* __restrict__ O)
{
    constexpr int CH = 128;
    __shared__ float Ks[CH][DHEAD];
    __shared__ float Vs[CH][DHEAD];

    const int h = blockIdx.x;
    const int b = blockIdx.y;
    const int m = threadIdx.x;

    float q[DHEAD];
    {
        const float* qp = Q + ((long)b * MROWS + m) * EMBD + h * DHEAD;
        #pragma unroll
        for (int i = 0; i < 4; i++) {
            float4 v4 = *(const float4*)(qp + i * 4);
            q[i*4+0]=v4.x; q[i*4+1]=v4.y; q[i*4+2]=v4.z; q[i*4+3]=v4.w;
        }
    }

    float mrun = -1e30f, l = 0.0f;
    float acc[DHEAD] = {};

    for (int t0 = 0; t0 < TTOK; t0 += CH) {
        const int cnt = min(CH, TTOK - t0);
        __syncthreads();
        for (int j = threadIdx.x; j < cnt * 4; j += 128) {
            const int r = j >> 2, c = (j & 3) * 4;
            const long base = ((long)b * TTOK + t0 + r) * EMBD + h * DHEAD + c;
            *(float4*)&Ks[r][c] = *(const float4*)(K + base);
            *(float4*)&Vs[r][c] = *(const float4*)(V + base);
        }
        __syncthreads();

        for (int tt = 0; tt < cnt; tt += 16) {
            float s[16];
            float cmax = -1e30f;
            #pragma unroll
            for (int j = 0; j < 16; j++) {
                if (tt + j < cnt) {
                    float d = 0.0f;
                    #pragma unroll
                    for (int i = 0; i < DHEAD; i++)
                        d = fmaf(q[i], Ks[tt + j][i], d);
                    s[j] = d * 0.25f;
                } else {
                    s[j] = -1e30f;
                }
                cmax = fmaxf(cmax, s[j]);
            }
            const float mnew = fmaxf(mrun, cmax);
            const float corr = __expf(mrun - mnew);
            l *= corr;
            #pragma unroll
            for (int i = 0; i < DHEAD; i++) acc[i] *= corr;
            #pragma unroll
            for (int j = 0; j < 16; j++) {
                const float p = __expf(s[j] - mnew);
                l += p;
                #pragma unroll
                for (int i = 0; i < DHEAD; i++)
                    acc[i] = fmaf(p, Vs[tt + j][i], acc[i]);
            }
            mrun = mnew;
        }
    }

    const float inv = 1.0f / l;
    float* op = O + ((long)b * MROWS + m) * EMBD + h * DHEAD;
    #pragma unroll
    for (int i = 0; i < 4; i++) {
        float4 o;
        o.x = acc[i*4+0]*inv; o.y = acc[i*4+1]*inv;
        o.z = acc[i*4+2]*inv; o.w = acc[i*4+3]*inv;
        *(float4*)(op + i * 4) = o;
    }
}

// =================== score2: 128x128 tiles + tanh/exp epilogue =============
__global__ void __launch_bounds__(256, 2)
score2_kernel(const float* __restrict__ MH, const float* __restrict__ jobs,
              const float* __restrict__ skip, const float* __restrict__ mask,
              float* __restrict__ out, float* __restrict__ sums)
{
    __shared__ float As[2][BK][ASTRIDE];
    __shared__ float Bs[2][BK][BN + 4];
    __shared__ float red[256];

    const int tid  = threadIdx.x;
    const int b    = blockIdx.z;
    const int col0 = blockIdx.x * BN;

    const int a_row = tid >> 1;
    const int a_k   = (tid & 1) * 8;
    const int tx = tid & 15;
    const int ty = tid >> 4;

    const float* arow = MH + ((long)b * MROWS + a_row) * EMBD;

    const int t_l = tid >> 1;           // tile-local col (0..127)
    const int t_g = col0 + t_l;
    const float* brow = (t_g < TTOK) ? jobs_row(jobs, skip, b, t_g) : nullptr;

    float4 av0, av1, bv0, bv1;
    av0 = *(const float4*)(arow + a_k);
    av1 = *(const float4*)(arow + a_k + 4);
    bv0 = bv1 = make_float4(0.f,0.f,0.f,0.f);
    if (brow) { bv0 = *(const float4*)(brow + a_k); bv1 = *(const float4*)(brow + a_k + 4); }
    {
        As[0][a_k+0][a_row]=av0.x; As[0][a_k+1][a_row]=av0.y;
        As[0][a_k+2][a_row]=av0.z; As[0][a_k+3][a_row]=av0.w;
        As[0][a_k+4][a_row]=av1.x; As[0][a_k+5][a_row]=av1.y;
        As[0][a_k+6][a_row]=av1.z; As[0][a_k+7][a_row]=av1.w;
        Bs[0][a_k+0][t_l]=bv0.x; Bs[0][a_k+1][t_l]=bv0.y;
        Bs[0][a_k+2][t_l]=bv0.z; Bs[0][a_k+3][t_l]=bv0.w;
        Bs[0][a_k+4][t_l]=bv1.x; Bs[0][a_k+5][t_l]=bv1.y;
        Bs[0][a_k+6][t_l]=bv1.z; Bs[0][a_k+7][t_l]=bv1.w;
    }
    __syncthreads();

    float acc[8][8] = {};

    #pragma unroll 1
    for (int ks = 0; ks < EMBD / BK; ks++) {
        const int cur = ks & 1;
        const bool has_next = (ks < EMBD / BK - 1);
        if (has_next) {
            const int k0 = (ks + 1) * BK;
            av0 = *(const float4*)(arow + k0 + a_k);
            av1 = *(const float4*)(arow + k0 + a_k + 4);
            if (brow) {
                bv0 = *(const float4*)(brow + k0 + a_k);
                bv1 = *(const float4*)(brow + k0 + a_k + 4);
            }
        }
        #pragma unroll
        for (int kk = 0; kk < BK; kk++) {
            float4 a0 = *(const float4*)&As[cur][kk][ty * 4];
            float4 a1 = *(const float4*)&As[cur][kk][64 + ty * 4];
            float4 b0 = *(const float4*)&Bs[cur][kk][tx * 4];
            float4 b1 = *(const float4*)&Bs[cur][kk][64 + tx * 4];
            float a[8] = {a0.x,a0.y,a0.z,a0.w,a1.x,a1.y,a1.z,a1.w};
            float bb[8] = {b0.x,b0.y,b0.z,b0.w,b1.x,b1.y,b1.z,b1.w};
            #pragma unroll
            for (int i = 0; i < 8; i++)
                #pragma unroll
                for (int j = 0; j < 8; j++)
                    acc[i][j] = fmaf(a[i], bb[j], acc[i][j]);
        }
        if (has_next) {
            const int nxt = 1 - cur;
            As[nxt][a_k+0][a_row]=av0.x; As[nxt][a_k+1][a_row]=av0.y;
            As[nxt][a_k+2][a_row]=av0.z; As[nxt][a_k+3][a_row]=av0.w;
            As[nxt][a_k+4][a_row]=av1.x; As[nxt][a_k+5][a_row]=av1.y;
            As[nxt][a_k+6][a_row]=av1.z; As[nxt][a_k+7][a_row]=av1.w;
            Bs[nxt][a_k+0][t_l]=bv0.x; Bs[nxt][a_k+1][t_l]=bv0.y;
            Bs[nxt][a_k+2][t_l]=bv0.z; Bs[nxt][a_k+3][t_l]=bv0.w;
            Bs[nxt][a_k+4][t_l]=bv1.x; Bs[nxt][a_k+5][t_l]=bv1.y;
            Bs[nxt][a_k+6][t_l]=bv1.z; Bs[nxt][a_k+7][t_l]=bv1.w;
        }
        __syncthreads();
    }

    float lsum = 0.0f;
    #pragma unroll
    for (int half = 0; half < 2; half++) {
        #pragma unroll
        for (int i = 0; i < 4; i++) {
            const int m = half * 64 + ty * 4 + i;
            const int ai = half * 4 + i;
            #pragma unroll
            for (int jh = 0; jh < 2; jh++) {
                #pragma unroll
                for (int j = 0; j < 4; j++) {
                    const int t = col0 + jh * 64 + tx * 4 + j;
                    if (t < TTOK) {
                        const float sc = acc[ai][jh * 4 + j] * 0.0625f;
                        const long li = (long)b * OUT_PER_B + (long)m * TTOK + t;
                        const float lg = 10.0f * tanhf(sc) + mask[li];
                        const float y = __expf(lg);
                        out[li] = y;
                        lsum += y;
                    }
                }
            }
        }
    }

    red[tid] = lsum;
    __syncthreads();
    #pragma unroll
    for (int s = 128; s > 0; s >>= 1) {
        if (tid < s) red[tid] += red[tid + s];
        __syncthreads();
    }
    if (tid == 0) atomicAdd(&sums[b], red[0]);
}

// =================== normalize (float4) ===================
__global__ void __launch_bounds__(256)
norm_kernel(float4* __restrict__ out, const float* __restrict__ sums, long n4)
{
    long i = (long)blockIdx.x * blockDim.x + threadIdx.x;
    const long stride = (long)gridDim.x * blockDim.x;
    const long per_b4 = OUT_PER_B / 4;
    for (; i < n4; i += stride) {
        const int b = (int)(i / per_b4);
        const float inv = 1.0f / sums[b];
        float4 v = out[i];
        v.x *= inv; v.y *= inv; v.z *= inv; v.w *= inv;
        out[i] = v;
    }
}

// =================== launch ===================
extern "C" void kernel_launch(void* const* d_in, const int* in_sizes, int n_in,
                              void* d_out, int out_size)
{
    const float* machine = (const float*)d_in[0];
    const float* jobs    = (const float*)d_in[1];
    const float* mask    = (const float*)d_in[2];
    const float* Wq3     = (const float*)d_in[3];
    const float* Wk      = (const float*)d_in[4];
    const float* Wv      = (const float*)d_in[5];
    const float* Wc      = (const float*)d_in[6];
    const float* bc      = (const float*)d_in[7];
    const float* skip    = (const float*)d_in[8];
    float* out = (float*)d_out;

    float *Qp, *Kp, *Vp, *Op, *MHp, *Sp;
    cudaGetSymbolAddress((void**)&Qp,  g_Q);
    cudaGetSymbolAddress((void**)&Kp,  g_K);
    cudaGetSymbolAddress((void**)&Vp,  g_V);
    cudaGetSymbolAddress((void**)&Op,  g_O);
    cudaGetSymbolAddress((void**)&MHp, g_MH);
    cudaGetSymbolAddress((void**)&Sp,  g_SUM);

    zero_sums_kernel<<<1, BATCH>>>(Sp);

    // Q projection: 8192 rows
    gemm128_kernel<0><<<dim3(EMBD / BN, (BATCH * MROWS) / BM, 1), 256>>>(
        machine, nullptr, Wq3, nullptr, nullptr, Qp, nullptr, BATCH * MROWS);

    // K + V projections (z selects): 32832 rows -> 257 row tiles
    const int kv_rows = BATCH * TTOK;
    gemm128_kernel<1><<<dim3(EMBD / BN, (kv_rows + BM - 1) / BM, 2), 256>>>(
        jobs, skip, Wk, Wv, nullptr, Kp, Vp, kv_rows);

    // attention
    attn_kernel<<<dim3(HEADS, BATCH), 128>>>(Qp, Kp, Vp, Op);

    // output projection + bias
    gemm128_kernel<2><<<dim3(EMBD / BN, (BATCH * MROWS) / BM, 1), 256>>>(
        Op, nullptr, Wc, nullptr, bc, MHp, nullptr, BATCH * MROWS);

    // score2 + clip + exp + per-batch sums
    score2_kernel<<<dim3((TTOK + BN - 1) / BN, 1, BATCH), 256>>>(
        MHp, jobs, skip, mask, out, Sp);

    // normalize
    const long n4 = (long)BATCH * OUT_PER_B / 4;
    int blocks = (int)((n4 + 255) / 256);
    if (blocks > 8192) blocks = 8192;
    norm_kernel<<<blocks, 256>>>((float4*)out, Sp, n4);
}

// round 3
// speedup vs baseline: 1.1986x; 1.0822x over previous
#include <cuda_runtime.h>
#include <cuda_bf16.h>
#include <math.h>

#define EMBD   256
#define HEADS  16
#define DHEAD  16
#define BATCH  64
#define MROWS  128
#define JJOBS  512
#define TTOK   513
#define OUT_PER_B (MROWS * TTOK)   // 65664

typedef unsigned long long ull;

__device__ float g_Q [BATCH * MROWS * EMBD];
__device__ float g_K [BATCH * TTOK  * EMBD];
__device__ float g_V [BATCH * TTOK  * EMBD];
__device__ float g_O [BATCH * MROWS * EMBD];
__device__ float g_MH[BATCH * MROWS * EMBD];
__device__ float g_SUM[BATCH];

// ---------------- packed f32x2 helpers (sm_103a) ----------------
__device__ __forceinline__ ull fma2(ull a, ull b, ull c) {
    ull d; asm("fma.rn.f32x2 %0, %1, %2, %3;" : "=l"(d) : "l"(a), "l"(b), "l"(c));
    return d;
}
__device__ __forceinline__ ull mul2(ull a, ull b) {
    ull d; asm("mul.rn.f32x2 %0, %1, %2;" : "=l"(d) : "l"(a), "l"(b));
    return d;
}
__device__ __forceinline__ ull bcast2(float x) {
    ull d; asm("mov.b64 %0, {%1, %2};" : "=l"(d) : "f"(x), "f"(x));
    return d;
}
__device__ __forceinline__ float2 unpack2(ull v) {
    float2 f; asm("mov.b64 {%0, %1}, %2;" : "=f"(f.x), "=f"(f.y) : "l"(v));
    return f;
}

__device__ __forceinline__ const float* jobs_row(const float* __restrict__ jobs,
                                                 const float* __restrict__ skip,
                                                 int b, int t) {
    return (t == 0) ? skip : jobs + ((long)b * JJOBS + (t - 1)) * EMBD;
}

__global__ void zero_sums_kernel(float* __restrict__ sums) {
    sums[threadIdx.x] = 0.0f;
}

// =================== 128x128x16 SGEMM, 8x8 microtile, f32x2, dbuf ==========
#define BM 128
#define BN 128
#define BK 16
#define ASTRIDE (BM + 4)

template <int MODE>   // 0: direct rows; 1: virtual jobs rows, z selects W/C; 2: +bias
__global__ void __launch_bounds__(256, 2)
gemm128_kernel(const float* __restrict__ X, const float* __restrict__ skip,
               const float* __restrict__ Wa, const float* __restrict__ Wb,
               const float* __restrict__ bias,
               float* __restrict__ Ca, float* __restrict__ Cb, int nrows)
{
    __shared__ float As[2][BK][ASTRIDE];
    __shared__ float Bs[2][BK][BN];

    const float* W = (MODE == 1 && blockIdx.z == 1) ? Wb : Wa;
    float*       C = (MODE == 1 && blockIdx.z == 1) ? Cb : Ca;

    const int tid  = threadIdx.x;
    const int row0 = blockIdx.y * BM;
    const int col0 = blockIdx.x * BN;

    const int a_row = tid >> 1;
    const int a_k   = (tid & 1) * 8;
    const int b_k   = tid >> 4;
    const int b_n   = (tid & 15) * 8;

    const int tx = tid & 15;
    const int ty = tid >> 4;

    const float* xrow;
    {
        int grow = row0 + a_row;
        if (grow > nrows - 1) grow = nrows - 1;
        if (MODE == 1) {
            const int b = grow / TTOK;
            const int t = grow - b * TTOK;
            xrow = jobs_row(X, skip, b, t);
        } else {
            xrow = X + (long)grow * EMBD;
        }
    }
    const float* wptr = W + (long)b_k * EMBD + col0 + b_n;

    float4 av0, av1, bv0, bv1;
    av0 = *(const float4*)(xrow + a_k);
    av1 = *(const float4*)(xrow + a_k + 4);
    bv0 = *(const float4*)(wptr);
    bv1 = *(const float4*)(wptr + 4);
    {
        As[0][a_k + 0][a_row] = av0.x; As[0][a_k + 1][a_row] = av0.y;
        As[0][a_k + 2][a_row] = av0.z; As[0][a_k + 3][a_row] = av0.w;
        As[0][a_k + 4][a_row] = av1.x; As[0][a_k + 5][a_row] = av1.y;
        As[0][a_k + 6][a_row] = av1.z; As[0][a_k + 7][a_row] = av1.w;
        *(float4*)&Bs[0][b_k][b_n]     = bv0;
        *(float4*)&Bs[0][b_k][b_n + 4] = bv1;
    }
    __syncthreads();

    ull acc2[8][4] = {};

    #pragma unroll 1
    for (int ks = 0; ks < EMBD / BK; ks++) {
        const int cur = ks & 1;
        const bool has_next = (ks < EMBD / BK - 1);
        if (has_next) {
            const int k0 = (ks + 1) * BK;
            av0 = *(const float4*)(xrow + k0 + a_k);
            av1 = *(const float4*)(xrow + k0 + a_k + 4);
            bv0 = *(const float4*)(wptr + (long)k0 * EMBD);
            bv1 = *(const float4*)(wptr + (long)k0 * EMBD + 4);
        }

        #pragma unroll
        for (int kk = 0; kk < BK; kk++) {
            float4 a0 = *(const float4*)&As[cur][kk][ty * 4];
            float4 a1 = *(const float4*)&As[cur][kk][64 + ty * 4];
            ulonglong2 p0 = *(const ulonglong2*)&Bs[cur][kk][tx * 4];
            ulonglong2 p1 = *(const ulonglong2*)&Bs[cur][kk][64 + tx * 4];
            ull B2[4] = {p0.x, p0.y, p1.x, p1.y};
            float a[8] = {a0.x,a0.y,a0.z,a0.w,a1.x,a1.y,a1.z,a1.w};
            #pragma unroll
            for (int i = 0; i < 8; i++) {
                const ull ai = bcast2(a[i]);
                #pragma unroll
                for (int j = 0; j < 4; j++)
                    acc2[i][j] = fma2(ai, B2[j], acc2[i][j]);
            }
        }

        if (has_next) {
            const int nxt = 1 - cur;
            As[nxt][a_k + 0][a_row] = av0.x; As[nxt][a_k + 1][a_row] = av0.y;
            As[nxt][a_k + 2][a_row] = av0.z; As[nxt][a_k + 3][a_row] = av0.w;
            As[nxt][a_k + 4][a_row] = av1.x; As[nxt][a_k + 5][a_row] = av1.y;
            As[nxt][a_k + 6][a_row] = av1.z; As[nxt][a_k + 7][a_row] = av1.w;
            *(float4*)&Bs[nxt][b_k][b_n]     = bv0;
            *(float4*)&Bs[nxt][b_k][b_n + 4] = bv1;
        }
        __syncthreads();
    }

    float4 bb0 = make_float4(0.f,0.f,0.f,0.f), bb1 = bb0;
    if (MODE == 2) {
        bb0 = *(const float4*)(bias + col0 + tx * 4);
        bb1 = *(const float4*)(bias + col0 + 64 + tx * 4);
    }

    #pragma unroll
    for (int half = 0; half < 2; half++) {
        #pragma unroll
        for (int i = 0; i < 4; i++) {
            const int r = row0 + half * 64 + ty * 4 + i;
            if (r < nrows) {
                const int ai = half * 4 + i;
                float2 c0 = unpack2(acc2[ai][0]);
                float2 c1 = unpack2(acc2[ai][1]);
                float2 c2 = unpack2(acc2[ai][2]);
                float2 c3 = unpack2(acc2[ai][3]);
                float4 o0, o1;
                o0.x = c0.x + bb0.x; o0.y = c0.y + bb0.y;
                o0.z = c1.x + bb0.z; o0.w = c1.y + bb0.w;
                o1.x = c2.x + bb1.x; o1.y = c2.y + bb1.y;
                o1.z = c3.x + bb1.z; o1.w = c3.y + bb1.w;
                *(float4*)(C + (long)r * EMBD + col0 + tx * 4)      = o0;
                *(float4*)(C + (long)r * EMBD + col0 + 64 + tx * 4) = o1;
            }
        }
    }
}

// =================== attention: 2-way T split, f32x2, 256 thr ==============
#define AT_CH 128
__global__ void __launch_bounds__(256)
attn_kernel(const float* __restrict__ Q, const float* __restrict__ K,
            const float* __restrict__ V, float* __restrict__ O)
{
    __shared__ float Ks[2][AT_CH][DHEAD];
    __shared__ float Vs[2][AT_CH][DHEAD];
    __shared__ float partM[128];
    __shared__ float partL[128];
    __shared__ ull   partA[128][8];

    const int h = blockIdx.x;
    const int b = blockIdx.y;
    const int tid = threadIdx.x;
    const int g = tid >> 7;        // half-group: 0 or 1
    const int m = tid & 127;       // query row

    // q packed into 8 f32x2 pairs
    ull q2[8];
    {
        const float* qp = Q + ((long)b * MROWS + m) * EMBD + h * DHEAD;
        #pragma unroll
        for (int p = 0; p < 4; p++) {
            ulonglong2 v = *(const ulonglong2*)(qp + p * 4);
            q2[2*p] = v.x; q2[2*p+1] = v.y;
        }
    }

    float mrun = -1e30f, l = 0.0f;
    ull acc2[8] = {};

    #pragma unroll 1
    for (int r = 0; r < 3; r++) {
        const int c  = 2 * r + g;
        const int t0 = c * AT_CH;
        const int cnt = (t0 < TTOK) ? min(AT_CH, TTOK - t0) : 0;

        __syncthreads();
        for (int j = m; j < cnt * 4; j += 128) {
            const int rr = j >> 2, cc = (j & 3) * 4;
            const long base = ((long)b * TTOK + t0 + rr) * EMBD + h * DHEAD + cc;
            *(float4*)&Ks[g][rr][cc] = *(const float4*)(K + base);
            *(float4*)&Vs[g][rr][cc] = *(const float4*)(V + base);
        }
        __syncthreads();

        for (int tt = 0; tt < cnt; tt += 16) {
            float s[16];
            float cmax = -1e30f;
            #pragma unroll
            for (int j = 0; j < 16; j++) {
                if (tt + j < cnt) {
                    const ulonglong2* kp = (const ulonglong2*)Ks[g][tt + j];
                    ulonglong2 k0 = kp[0], k1 = kp[1], k2v = kp[2], k3 = kp[3];
                    ull d2 = mul2(q2[0], k0.x);
                    d2 = fma2(q2[1], k0.y, d2);
                    d2 = fma2(q2[2], k1.x, d2);
                    d2 = fma2(q2[3], k1.y, d2);
                    d2 = fma2(q2[4], k2v.x, d2);
                    d2 = fma2(q2[5], k2v.y, d2);
                    d2 = fma2(q2[6], k3.x, d2);
                    d2 = fma2(q2[7], k3.y, d2);
                    float2 f = unpack2(d2);
                    s[j] = (f.x + f.y) * 0.25f;
                } else {
                    s[j] = -1e30f;
                }
                cmax = fmaxf(cmax, s[j]);
            }
            const float mnew = fmaxf(mrun, cmax);
            const float corr = __expf(mrun - mnew);
            l *= corr;
            const ull cb = bcast2(corr);
            #pragma unroll
            for (int p = 0; p < 8; p++) acc2[p] = mul2(acc2[p], cb);
            #pragma unroll
            for (int j = 0; j < 16; j++) {
                const float pw = __expf(s[j] - mnew);
                l += pw;
                if (tt + j < cnt) {
                    const ull pb = bcast2(pw);
                    const ulonglong2* vp = (const ulonglong2*)Vs[g][tt + j];
                    ulonglong2 v0 = vp[0], v1 = vp[1], v2v = vp[2], v3 = vp[3];
                    acc2[0] = fma2(pb, v0.x, acc2[0]);
                    acc2[1] = fma2(pb, v0.y, acc2[1]);
                    acc2[2] = fma2(pb, v1.x, acc2[2]);
                    acc2[3] = fma2(pb, v1.y, acc2[3]);
                    acc2[4] = fma2(pb, v2v.x, acc2[4]);
                    acc2[5] = fma2(pb, v2v.y, acc2[5]);
                    acc2[6] = fma2(pb, v3.x, acc2[6]);
                    acc2[7] = fma2(pb, v3.y, acc2[7]);
                }
            }
            mrun = mnew;
        }
    }

    __syncthreads();
    if (g == 1) {
        partM[m] = mrun;
        partL[m] = l;
        #pragma unroll
        for (int p = 0; p < 8; p++) partA[m][p] = acc2[p];
    }
    __syncthreads();
    if (g == 0) {
        const float m2 = partM[m], l2 = partL[m];
        const float mn = fmaxf(mrun, m2);
        const float c1 = __expf(mrun - mn);
        const float c2f = __expf(m2 - mn);
        const float lt = l * c1 + l2 * c2f;
        const float inv = 1.0f / lt;
        const float w1 = c1 * inv, w2 = c2f * inv;

        float* op = O + ((long)b * MROWS + m) * EMBD + h * DHEAD;
        #pragma unroll
        for (int p = 0; p < 4; p++) {
            float2 x0 = unpack2(acc2[2*p]);
            float2 x1 = unpack2(acc2[2*p+1]);
            float2 y0 = unpack2(partA[m][2*p]);
            float2 y1 = unpack2(partA[m][2*p+1]);
            float4 o;
            o.x = x0.x * w1 + y0.x * w2;
            o.y = x0.y * w1 + y0.y * w2;
            o.z = x1.x * w1 + y1.x * w2;
            o.w = x1.y * w1 + y1.y * w2;
            *(float4*)(op + p * 4) = o;
        }
    }
}

// =================== score2: 128x128 tiles, f32x2, tanh/exp epilogue =======
__global__ void __launch_bounds__(256, 2)
score2_kernel(const float* __restrict__ MH, const float* __restrict__ jobs,
              const float* __restrict__ skip, const float* __restrict__ mask,
              float* __restrict__ out, float* __restrict__ sums)
{
    __shared__ float As[2][BK][ASTRIDE];
    __shared__ float Bs[2][BK][BN + 4];
    __shared__ float red[256];

    const int tid  = threadIdx.x;
    const int b    = blockIdx.z;
    const int col0 = blockIdx.x * BN;

    const int a_row = tid >> 1;
    const int a_k   = (tid & 1) * 8;
    const int tx = tid & 15;
    const int ty = tid >> 4;

    const float* arow = MH + ((long)b * MROWS + a_row) * EMBD;

    const int t_l = tid >> 1;
    const int t_g = col0 + t_l;
    const float* brow = (t_g < TTOK) ? jobs_row(jobs, skip, b, t_g) : nullptr;

    float4 av0, av1, bv0, bv1;
    av0 = *(const float4*)(arow + a_k);
    av1 = *(const float4*)(arow + a_k + 4);
    bv0 = bv1 = make_float4(0.f,0.f,0.f,0.f);
    if (brow) { bv0 = *(const float4*)(brow + a_k); bv1 = *(const float4*)(brow + a_k + 4); }
    {
        As[0][a_k+0][a_row]=av0.x; As[0][a_k+1][a_row]=av0.y;
        As[0][a_k+2][a_row]=av0.z; As[0][a_k+3][a_row]=av0.w;
        As[0][a_k+4][a_row]=av1.x; As[0][a_k+5][a_row]=av1.y;
        As[0][a_k+6][a_row]=av1.z; As[0][a_k+7][a_row]=av1.w;
        Bs[0][a_k+0][t_l]=bv0.x; Bs[0][a_k+1][t_l]=bv0.y;
        Bs[0][a_k+2][t_l]=bv0.z; Bs[0][a_k+3][t_l]=bv0.w;
        Bs[0][a_k+4][t_l]=bv1.x; Bs[0][a_k+5][t_l]=bv1.y;
        Bs[0][a_k+6][t_l]=bv1.z; Bs[0][a_k+7][t_l]=bv1.w;
    }
    __syncthreads();

    ull acc2[8][4] = {};

    #pragma unroll 1
    for (int ks = 0; ks < EMBD / BK; ks++) {
        const int cur = ks & 1;
        const bool has_next = (ks < EMBD / BK - 1);
        if (has_next) {
            const int k0 = (ks + 1) * BK;
            av0 = *(const float4*)(arow + k0 + a_k);
            av1 = *(const float4*)(arow + k0 + a_k + 4);
            if (brow) {
                bv0 = *(const float4*)(brow + k0 + a_k);
                bv1 = *(const float4*)(brow + k0 + a_k + 4);
            }
        }
        #pragma unroll
        for (int kk = 0; kk < BK; kk++) {
            float4 a0 = *(const float4*)&As[cur][kk][ty * 4];
            float4 a1 = *(const float4*)&As[cur][kk][64 + ty * 4];
            ulonglong2 p0 = *(const ulonglong2*)&Bs[cur][kk][tx * 4];
            ulonglong2 p1 = *(const ulonglong2*)&Bs[cur][kk][64 + tx * 4];
            ull B2[4] = {p0.x, p0.y, p1.x, p1.y};
            float a[8] = {a0.x,a0.y,a0.z,a0.w,a1.x,a1.y,a1.z,a1.w};
            #pragma unroll
            for (int i = 0; i < 8; i++) {
                const ull ai = bcast2(a[i]);
                #pragma unroll
                for (int j = 0; j < 4; j++)
                    acc2[i][j] = fma2(ai, B2[j], acc2[i][j]);
            }
        }
        if (has_next) {
            const int nxt = 1 - cur;
            As[nxt][a_k+0][a_row]=av0.x; As[nxt][a_k+1][a_row]=av0.y;
            As[nxt][a_k+2][a_row]=av0.z; As[nxt][a_k+3][a_row]=av0.w;
            As[nxt][a_k+4][a_row]=av1.x; As[nxt][a_k+5][a_row]=av1.y;
            As[nxt][a_k+6][a_row]=av1.z; As[nxt][a_k+7][a_row]=av1.w;
            Bs[nxt][a_k+0][t_l]=bv0.x; Bs[nxt][a_k+1][t_l]=bv0.y;
            Bs[nxt][a_k+2][t_l]=bv0.z; Bs[nxt][a_k+3][t_l]=bv0.w;
            Bs[nxt][a_k+4][t_l]=bv1.x; Bs[nxt][a_k+5][t_l]=bv1.y;
            Bs[nxt][a_k+6][t_l]=bv1.z; Bs[nxt][a_k+7][t_l]=bv1.w;
        }
        __syncthreads();
    }

    float lsum = 0.0f;
    #pragma unroll
    for (int half = 0; half < 2; half++) {
        #pragma unroll
        for (int i = 0; i < 4; i++) {
            const int m = half * 64 + ty * 4 + i;
            const int ai = half * 4 + i;
            #pragma unroll
            for (int jh = 0; jh < 2; jh++) {
                #pragma unroll
                for (int jj = 0; jj < 2; jj++) {
                    float2 v = unpack2(acc2[ai][jh * 2 + jj]);
                    const int t = col0 + jh * 64 + tx * 4 + jj * 2;
                    if (t < TTOK) {
                        const long li = (long)b * OUT_PER_B + (long)m * TTOK + t;
                        const float lg = 10.0f * tanhf(v.x * 0.0625f) + mask[li];
                        const float y = __expf(lg);
                        out[li] = y;
                        lsum += y;
                    }
                    if (t + 1 < TTOK) {
                        const long li = (long)b * OUT_PER_B + (long)m * TTOK + t + 1;
                        const float lg = 10.0f * tanhf(v.y * 0.0625f) + mask[li];
                        const float y = __expf(lg);
                        out[li] = y;
                        lsum += y;
                    }
                }
            }
        }
    }

    red[tid] = lsum;
    __syncthreads();
    #pragma unroll
    for (int s = 128; s > 0; s >>= 1) {
        if (tid < s) red[tid] += red[tid + s];
        __syncthreads();
    }
    if (tid == 0) atomicAdd(&sums[b], red[0]);
}

// =================== normalize (float4) ===================
__global__ void __launch_bounds__(256)
norm_kernel(float4* __restrict__ out, const float* __restrict__ sums, long n4)
{
    long i = (long)blockIdx.x * blockDim.x + threadIdx.x;
    const long stride = (long)gridDim.x * blockDim.x;
    const long per_b4 = OUT_PER_B / 4;
    for (; i < n4; i += stride) {
        const int b = (int)(i / per_b4);
        const float inv = 1.0f / sums[b];
        float4 v = out[i];
        v.x *= inv; v.y *= inv; v.z *= inv; v.w *= inv;
        out[i] = v;
    }
}

// =================== launch ===================
extern "C" void kernel_launch(void* const* d_in, const int* in_sizes, int n_in,
                              void* d_out, int out_size)
{
    const float* machine = (const float*)d_in[0];
    const float* jobs    = (const float*)d_in[1];
    const float* mask    = (const float*)d_in[2];
    const float* Wq3     = (const float*)d_in[3];
    const float* Wk      = (const float*)d_in[4];
    const float* Wv      = (const float*)d_in[5];
    const float* Wc      = (const float*)d_in[6];
    const float* bc      = (const float*)d_in[7];
    const float* skip    = (const float*)d_in[8];
    float* out = (float*)d_out;

    float *Qp, *Kp, *Vp, *Op, *MHp, *Sp;
    cudaGetSymbolAddress((void**)&Qp,  g_Q);
    cudaGetSymbolAddress((void**)&Kp,  g_K);
    cudaGetSymbolAddress((void**)&Vp,  g_V);
    cudaGetSymbolAddress((void**)&Op,  g_O);
    cudaGetSymbolAddress((void**)&MHp, g_MH);
    cudaGetSymbolAddress((void**)&Sp,  g_SUM);

    zero_sums_kernel<<<1, BATCH>>>(Sp);

    gemm128_kernel<0><<<dim3(EMBD / BN, (BATCH * MROWS) / BM, 1), 256>>>(
        machine, nullptr, Wq3, nullptr, nullptr, Qp, nullptr, BATCH * MROWS);

    const int kv_rows = BATCH * TTOK;
    gemm128_kernel<1><<<dim3(EMBD / BN, (kv_rows + BM - 1) / BM, 2), 256>>>(
        jobs, skip, Wk, Wv, nullptr, Kp, Vp, kv_rows);

    attn_kernel<<<dim3(HEADS, BATCH), 256>>>(Qp, Kp, Vp, Op);

    gemm128_kernel<2><<<dim3(EMBD / BN, (BATCH * MROWS) / BM, 1), 256>>>(
        Op, nullptr, Wc, nullptr, bc, MHp, nullptr, BATCH * MROWS);

    score2_kernel<<<dim3((TTOK + BN - 1) / BN, 1, BATCH), 256>>>(
        MHp, jobs, skip, mask, out, Sp);

    const long n4 = (long)BATCH * OUT_PER_B / 4;
    int blocks = (int)((n4 + 255) / 256);
    if (blocks > 8192) blocks = 8192;
    norm_kernel<<<blocks, 256>>>((float4*)out, Sp, n4);
}

// round 4
// speedup vs baseline: 1.2920x; 1.0780x over previous
#include <cuda_runtime.h>
#include <cuda_bf16.h>
#include <math.h>

#define EMBD   256
#define HEADS  16
#define DHEAD  16
#define BATCH  64
#define MROWS  128
#define JJOBS  512
#define TTOK   513
#define OUT_PER_B (MROWS * TTOK)   // 65664

typedef unsigned long long ull;

__device__ float g_Q [BATCH * MROWS * EMBD];
__device__ float g_K [BATCH * TTOK  * EMBD];
__device__ float g_V [BATCH * TTOK  * EMBD];
__device__ float g_O [BATCH * MROWS * EMBD];
__device__ float g_MH[BATCH * MROWS * EMBD];
__device__ float g_SUM[BATCH];

// ---------------- packed f32x2 helpers (sm_103a) ----------------
__device__ __forceinline__ ull fma2(ull a, ull b, ull c) {
    ull d; asm("fma.rn.f32x2 %0, %1, %2, %3;" : "=l"(d) : "l"(a), "l"(b), "l"(c));
    return d;
}
__device__ __forceinline__ ull mul2(ull a, ull b) {
    ull d; asm("mul.rn.f32x2 %0, %1, %2;" : "=l"(d) : "l"(a), "l"(b));
    return d;
}
__device__ __forceinline__ ull bcast2(float x) {
    ull d; asm("mov.b64 %0, {%1, %2};" : "=l"(d) : "f"(x), "f"(x));
    return d;
}
__device__ __forceinline__ float2 unpack2(ull v) {
    float2 f; asm("mov.b64 {%0, %1}, %2;" : "=f"(f.x), "=f"(f.y) : "l"(v));
    return f;
}

__device__ __forceinline__ const float* jobs_row(const float* __restrict__ jobs,
                                                 const float* __restrict__ skip,
                                                 int b, int t) {
    return (t == 0) ? skip : jobs + ((long)b * JJOBS + (t - 1)) * EMBD;
}

__global__ void zero_sums_kernel(float* __restrict__ sums) {
    sums[threadIdx.x] = 0.0f;
}

// =================== tiles ===================
#define BM 128
#define BN 128
#define BK 16
#define ASTRIDE (BM + 4)

// GEMM inner-loop macro body shared by the three GEMM-shaped kernels.
#define GEMM_MICRO(cur)                                                        \
    _Pragma("unroll")                                                          \
    for (int kk = 0; kk < BK; kk++) {                                          \
        float4 a0 = *(const float4*)&As[cur][kk][ty * 4];                      \
        float4 a1 = *(const float4*)&As[cur][kk][64 + ty * 4];                 \
        ulonglong2 p0 = *(const ulonglong2*)&Bs[cur][kk][tx * 4];              \
        ulonglong2 p1 = *(const ulonglong2*)&Bs[cur][kk][64 + tx * 4];         \
        ull B2[4] = {p0.x, p0.y, p1.x, p1.y};                                  \
        float a[8] = {a0.x,a0.y,a0.z,a0.w,a1.x,a1.y,a1.z,a1.w};                \
        _Pragma("unroll")                                                      \
        for (int i = 0; i < 8; i++) {                                          \
            const ull ai = bcast2(a[i]);                                       \
            _Pragma("unroll")                                                  \
            for (int j = 0; j < 4; j++)                                        \
                acc2[i][j] = fma2(ai, B2[j], acc2[i][j]);                      \
        }                                                                      \
    }

// =================== merged projection kernel (Q, K, V) ====================
// z=0: K = jobs_virtual @ Wk   (32832 rows)
// z=1: V = jobs_virtual @ Wv   (32832 rows)
// z=2: Q = machine @ Wq3       (8192 rows; excess row-tiles exit)
__global__ void __launch_bounds__(256, 2)
proj_kernel(const float* __restrict__ jobs, const float* __restrict__ skip,
            const float* __restrict__ machine,
            const float* __restrict__ Wk, const float* __restrict__ Wv,
            const float* __restrict__ Wq,
            float* __restrict__ Kout, float* __restrict__ Vout,
            float* __restrict__ Qout)
{
    __shared__ float As[2][BK][ASTRIDE];
    __shared__ float Bs[2][BK][BN];

    const int z = blockIdx.z;
    const int row0 = blockIdx.y * BM;
    const int nrows = (z == 2) ? (BATCH * MROWS) : (BATCH * TTOK);
    if (row0 >= nrows) return;

    const float* W = (z == 0) ? Wk : (z == 1) ? Wv : Wq;
    float*       C = (z == 0) ? Kout : (z == 1) ? Vout : Qout;

    const int tid  = threadIdx.x;
    const int col0 = blockIdx.x * BN;

    const int a_row = tid >> 1;
    const int a_k   = (tid & 1) * 8;
    const int b_k   = tid >> 4;
    const int b_n   = (tid & 15) * 8;
    const int tx = tid & 15;
    const int ty = tid >> 4;

    const float* xrow;
    {
        int grow = row0 + a_row;
        if (grow > nrows - 1) grow = nrows - 1;
        if (z == 2) {
            xrow = machine + (long)grow * EMBD;
        } else {
            const int b = grow / TTOK;
            const int t = grow - b * TTOK;
            xrow = jobs_row(jobs, skip, b, t);
        }
    }
    const float* wptr = W + (long)b_k * EMBD + col0 + b_n;

    float4 av0, av1, bv0, bv1;
    av0 = *(const float4*)(xrow + a_k);
    av1 = *(const float4*)(xrow + a_k + 4);
    bv0 = *(const float4*)(wptr);
    bv1 = *(const float4*)(wptr + 4);
    As[0][a_k+0][a_row]=av0.x; As[0][a_k+1][a_row]=av0.y;
    As[0][a_k+2][a_row]=av0.z; As[0][a_k+3][a_row]=av0.w;
    As[0][a_k+4][a_row]=av1.x; As[0][a_k+5][a_row]=av1.y;
    As[0][a_k+6][a_row]=av1.z; As[0][a_k+7][a_row]=av1.w;
    *(float4*)&Bs[0][b_k][b_n]     = bv0;
    *(float4*)&Bs[0][b_k][b_n + 4] = bv1;
    __syncthreads();

    ull acc2[8][4] = {};

    #pragma unroll 1
    for (int ks = 0; ks < EMBD / BK; ks++) {
        const int cur = ks & 1;
        const bool has_next = (ks < EMBD / BK - 1);
        if (has_next) {
            const int k0 = (ks + 1) * BK;
            av0 = *(const float4*)(xrow + k0 + a_k);
            av1 = *(const float4*)(xrow + k0 + a_k + 4);
            bv0 = *(const float4*)(wptr + (long)k0 * EMBD);
            bv1 = *(const float4*)(wptr + (long)k0 * EMBD + 4);
        }
        GEMM_MICRO(cur)
        if (has_next) {
            const int nxt = 1 - cur;
            As[nxt][a_k+0][a_row]=av0.x; As[nxt][a_k+1][a_row]=av0.y;
            As[nxt][a_k+2][a_row]=av0.z; As[nxt][a_k+3][a_row]=av0.w;
            As[nxt][a_k+4][a_row]=av1.x; As[nxt][a_k+5][a_row]=av1.y;
            As[nxt][a_k+6][a_row]=av1.z; As[nxt][a_k+7][a_row]=av1.w;
            *(float4*)&Bs[nxt][b_k][b_n]     = bv0;
            *(float4*)&Bs[nxt][b_k][b_n + 4] = bv1;
        }
        __syncthreads();
    }

    #pragma unroll
    for (int half = 0; half < 2; half++) {
        #pragma unroll
        for (int i = 0; i < 4; i++) {
            const int r = row0 + half * 64 + ty * 4 + i;
            if (r < nrows) {
                const int ai = half * 4 + i;
                float2 c0 = unpack2(acc2[ai][0]);
                float2 c1 = unpack2(acc2[ai][1]);
                float2 c2 = unpack2(acc2[ai][2]);
                float2 c3 = unpack2(acc2[ai][3]);
                float4 o0 = make_float4(c0.x, c0.y, c1.x, c1.y);
                float4 o1 = make_float4(c2.x, c2.y, c3.x, c3.y);
                *(float4*)(C + (long)r * EMBD + col0 + tx * 4)      = o0;
                *(float4*)(C + (long)r * EMBD + col0 + 64 + tx * 4) = o1;
            }
        }
    }
}

// =================== Wc projection (+bias) ====================
__global__ void __launch_bounds__(256, 2)
wc_kernel(const float* __restrict__ X, const float* __restrict__ W,
          const float* __restrict__ bias, float* __restrict__ C)
{
    __shared__ float As[2][BK][ASTRIDE];
    __shared__ float Bs[2][BK][BN];

    const int tid  = threadIdx.x;
    const int row0 = blockIdx.y * BM;
    const int col0 = blockIdx.x * BN;

    const int a_row = tid >> 1;
    const int a_k   = (tid & 1) * 8;
    const int b_k   = tid >> 4;
    const int b_n   = (tid & 15) * 8;
    const int tx = tid & 15;
    const int ty = tid >> 4;

    const float* xrow = X + (long)(row0 + a_row) * EMBD;
    const float* wptr = W + (long)b_k * EMBD + col0 + b_n;

    float4 av0, av1, bv0, bv1;
    av0 = *(const float4*)(xrow + a_k);
    av1 = *(const float4*)(xrow + a_k + 4);
    bv0 = *(const float4*)(wptr);
    bv1 = *(const float4*)(wptr + 4);
    As[0][a_k+0][a_row]=av0.x; As[0][a_k+1][a_row]=av0.y;
    As[0][a_k+2][a_row]=av0.z; As[0][a_k+3][a_row]=av0.w;
    As[0][a_k+4][a_row]=av1.x; As[0][a_k+5][a_row]=av1.y;
    As[0][a_k+6][a_row]=av1.z; As[0][a_k+7][a_row]=av1.w;
    *(float4*)&Bs[0][b_k][b_n]     = bv0;
    *(float4*)&Bs[0][b_k][b_n + 4] = bv1;
    __syncthreads();

    ull acc2[8][4] = {};

    #pragma unroll 1
    for (int ks = 0; ks < EMBD / BK; ks++) {
        const int cur = ks & 1;
        const bool has_next = (ks < EMBD / BK - 1);
        if (has_next) {
            const int k0 = (ks + 1) * BK;
            av0 = *(const float4*)(xrow + k0 + a_k);
            av1 = *(const float4*)(xrow + k0 + a_k + 4);
            bv0 = *(const float4*)(wptr + (long)k0 * EMBD);
            bv1 = *(const float4*)(wptr + (long)k0 * EMBD + 4);
        }
        GEMM_MICRO(cur)
        if (has_next) {
            const int nxt = 1 - cur;
            As[nxt][a_k+0][a_row]=av0.x; As[nxt][a_k+1][a_row]=av0.y;
            As[nxt][a_k+2][a_row]=av0.z; As[nxt][a_k+3][a_row]=av0.w;
            As[nxt][a_k+4][a_row]=av1.x; As[nxt][a_k+5][a_row]=av1.y;
            As[nxt][a_k+6][a_row]=av1.z; As[nxt][a_k+7][a_row]=av1.w;
            *(float4*)&Bs[nxt][b_k][b_n]     = bv0;
            *(float4*)&Bs[nxt][b_k][b_n + 4] = bv1;
        }
        __syncthreads();
    }

    float4 bb0 = *(const float4*)(bias + col0 + tx * 4);
    float4 bb1 = *(const float4*)(bias + col0 + 64 + tx * 4);

    #pragma unroll
    for (int half = 0; half < 2; half++) {
        #pragma unroll
        for (int i = 0; i < 4; i++) {
            const int r = row0 + half * 64 + ty * 4 + i;
            const int ai = half * 4 + i;
            float2 c0 = unpack2(acc2[ai][0]);
            float2 c1 = unpack2(acc2[ai][1]);
            float2 c2 = unpack2(acc2[ai][2]);
            float2 c3 = unpack2(acc2[ai][3]);
            float4 o0 = make_float4(c0.x+bb0.x, c0.y+bb0.y, c1.x+bb0.z, c1.y+bb0.w);
            float4 o1 = make_float4(c2.x+bb1.x, c2.y+bb1.y, c3.x+bb1.z, c3.y+bb1.w);
            *(float4*)(C + (long)r * EMBD + col0 + tx * 4)      = o0;
            *(float4*)(C + (long)r * EMBD + col0 + 64 + tx * 4) = o1;
        }
    }
}

// =================== attention: 4 full chunks + scalar tail ================
// grid (H, B), block 128 (1 query/thread); no bounds checks in hot loop.
__global__ void __launch_bounds__(128)
attn_kernel(const float* __restrict__ Q, const float* __restrict__ K,
            const float* __restrict__ V, float* __restrict__ O)
{
    __shared__ float Ks[128][DHEAD];
    __shared__ float Vs[128][DHEAD];

    const int h = blockIdx.x;
    const int b = blockIdx.y;
    const int m = threadIdx.x;

    ull q2[8];
    {
        const float* qp = Q + ((long)b * MROWS + m) * EMBD + h * DHEAD;
        #pragma unroll
        for (int p = 0; p < 4; p++) {
            ulonglong2 v = *(const ulonglong2*)(qp + p * 4);
            q2[2*p] = v.x; q2[2*p+1] = v.y;
        }
    }

    float mrun = -1e30f, l = 0.0f;
    ull acc2[8] = {};

    #pragma unroll 1
    for (int c = 0; c < 4; c++) {
        const int t0 = c * 128;
        __syncthreads();
        #pragma unroll
        for (int j = 0; j < 4; j++) {
            const int idx = m + j * 128;        // 0..511
            const int rr = idx >> 2, cc = (idx & 3) * 4;
            const long base = ((long)b * TTOK + t0 + rr) * EMBD + h * DHEAD + cc;
            *(float4*)&Ks[rr][cc] = *(const float4*)(K + base);
            *(float4*)&Vs[rr][cc] = *(const float4*)(V + base);
        }
        __syncthreads();

        #pragma unroll 1
        for (int tt = 0; tt < 128; tt += 8) {
            float s[8];
            #pragma unroll
            for (int j = 0; j < 8; j++) {
                const ulonglong2* kp = (const ulonglong2*)Ks[tt + j];
                ulonglong2 k0 = kp[0], k1 = kp[1];
                ull d2 = mul2(q2[0], k0.x);
                d2 = fma2(q2[1], k0.y, d2);
                d2 = fma2(q2[2], k1.x, d2);
                d2 = fma2(q2[3], k1.y, d2);
                ulonglong2 k2v = kp[2], k3 = kp[3];
                d2 = fma2(q2[4], k2v.x, d2);
                d2 = fma2(q2[5], k2v.y, d2);
                d2 = fma2(q2[6], k3.x, d2);
                d2 = fma2(q2[7], k3.y, d2);
                float2 f = unpack2(d2);
                s[j] = (f.x + f.y) * 0.25f;
            }
            float cmax = fmaxf(fmaxf(fmaxf(s[0], s[1]), fmaxf(s[2], s[3])),
                               fmaxf(fmaxf(s[4], s[5]), fmaxf(s[6], s[7])));
            const float mnew = fmaxf(mrun, cmax);
            const float corr = __expf(mrun - mnew);
            l *= corr;
            const ull cb = bcast2(corr);
            #pragma unroll
            for (int p = 0; p < 8; p++) acc2[p] = mul2(acc2[p], cb);
            #pragma unroll
            for (int j = 0; j < 8; j++) {
                const float pw = __expf(s[j] - mnew);
                l += pw;
                const ull pb = bcast2(pw);
                const ulonglong2* vp = (const ulonglong2*)Vs[tt + j];
                ulonglong2 v0 = vp[0], v1 = vp[1];
                acc2[0] = fma2(pb, v0.x, acc2[0]);
                acc2[1] = fma2(pb, v0.y, acc2[1]);
                acc2[2] = fma2(pb, v1.x, acc2[2]);
                acc2[3] = fma2(pb, v1.y, acc2[3]);
                ulonglong2 v2v = vp[2], v3 = vp[3];
                acc2[4] = fma2(pb, v2v.x, acc2[4]);
                acc2[5] = fma2(pb, v2v.y, acc2[5]);
                acc2[6] = fma2(pb, v3.x, acc2[6]);
                acc2[7] = fma2(pb, v3.y, acc2[7]);
            }
            mrun = mnew;
        }
    }

    // tail token t = 512
    {
        const long base = ((long)b * TTOK + 512) * EMBD + h * DHEAD;
        const ulonglong2* kp = (const ulonglong2*)(K + base);
        ulonglong2 k0 = kp[0], k1 = kp[1], k2v = kp[2], k3 = kp[3];
        ull d2 = mul2(q2[0], k0.x);
        d2 = fma2(q2[1], k0.y, d2);
        d2 = fma2(q2[2], k1.x, d2);
        d2 = fma2(q2[3], k1.y, d2);
        d2 = fma2(q2[4], k2v.x, d2);
        d2 = fma2(q2[5], k2v.y, d2);
        d2 = fma2(q2[6], k3.x, d2);
        d2 = fma2(q2[7], k3.y, d2);
        float2 f = unpack2(d2);
        const float s = (f.x + f.y) * 0.25f;
        const float mnew = fmaxf(mrun, s);
        const float corr = __expf(mrun - mnew);
        const float pw = __expf(s - mnew);
        l = l * corr + pw;
        const ull cb = bcast2(corr);
        const ull pb = bcast2(pw);
        const ulonglong2* vp = (const ulonglong2*)(V + base);
        ulonglong2 v0 = vp[0], v1 = vp[1], v2v = vp[2], v3 = vp[3];
        acc2[0] = fma2(pb, v0.x,  mul2(acc2[0], cb));
        acc2[1] = fma2(pb, v0.y,  mul2(acc2[1], cb));
        acc2[2] = fma2(pb, v1.x,  mul2(acc2[2], cb));
        acc2[3] = fma2(pb, v1.y,  mul2(acc2[3], cb));
        acc2[4] = fma2(pb, v2v.x, mul2(acc2[4], cb));
        acc2[5] = fma2(pb, v2v.y, mul2(acc2[5], cb));
        acc2[6] = fma2(pb, v3.x,  mul2(acc2[6], cb));
        acc2[7] = fma2(pb, v3.y,  mul2(acc2[7], cb));
    }

    const float inv = 1.0f / l;
    float* op = O + ((long)b * MROWS + m) * EMBD + h * DHEAD;
    #pragma unroll
    for (int p = 0; p < 4; p++) {
        float2 x0 = unpack2(acc2[2*p]);
        float2 x1 = unpack2(acc2[2*p+1]);
        float4 o = make_float4(x0.x * inv, x0.y * inv, x1.x * inv, x1.y * inv);
        *(float4*)(op + p * 4) = o;
    }
}

// =================== score2: 128x128 tiles + tanh/exp epilogue =============
__global__ void __launch_bounds__(256, 2)
score2_kernel(const float* __restrict__ MH, const float* __restrict__ jobs,
              const float* __restrict__ skip, const float* __restrict__ mask,
              float* __restrict__ out, float* __restrict__ sums)
{
    __shared__ float As[2][BK][ASTRIDE];
    __shared__ float Bs[2][BK][BN + 4];
    __shared__ float red[256];

    const int tid  = threadIdx.x;
    const int b    = blockIdx.z;
    const int col0 = blockIdx.x * BN;

    const int a_row = tid >> 1;
    const int a_k   = (tid & 1) * 8;
    const int tx = tid & 15;
    const int ty = tid >> 4;

    const float* arow = MH + ((long)b * MROWS + a_row) * EMBD;

    const int t_l = tid >> 1;
    const int t_g = col0 + t_l;
    const float* brow = (t_g < TTOK) ? jobs_row(jobs, skip, b, t_g) : nullptr;

    float4 av0, av1, bv0, bv1;
    av0 = *(const float4*)(arow + a_k);
    av1 = *(const float4*)(arow + a_k + 4);
    bv0 = bv1 = make_float4(0.f,0.f,0.f,0.f);
    if (brow) { bv0 = *(const float4*)(brow + a_k); bv1 = *(const float4*)(brow + a_k + 4); }
    As[0][a_k+0][a_row]=av0.x; As[0][a_k+1][a_row]=av0.y;
    As[0][a_k+2][a_row]=av0.z; As[0][a_k+3][a_row]=av0.w;
    As[0][a_k+4][a_row]=av1.x; As[0][a_k+5][a_row]=av1.y;
    As[0][a_k+6][a_row]=av1.z; As[0][a_k+7][a_row]=av1.w;
    Bs[0][a_k+0][t_l]=bv0.x; Bs[0][a_k+1][t_l]=bv0.y;
    Bs[0][a_k+2][t_l]=bv0.z; Bs[0][a_k+3][t_l]=bv0.w;
    Bs[0][a_k+4][t_l]=bv1.x; Bs[0][a_k+5][t_l]=bv1.y;
    Bs[0][a_k+6][t_l]=bv1.z; Bs[0][a_k+7][t_l]=bv1.w;
    __syncthreads();

    ull acc2[8][4] = {};

    #pragma unroll 1
    for (int ks = 0; ks < EMBD / BK; ks++) {
        const int cur = ks & 1;
        const bool has_next = (ks < EMBD / BK - 1);
        if (has_next) {
            const int k0 = (ks + 1) * BK;
            av0 = *(const float4*)(arow + k0 + a_k);
            av1 = *(const float4*)(arow + k0 + a_k + 4);
            if (brow) {
                bv0 = *(const float4*)(brow + k0 + a_k);
                bv1 = *(const float4*)(brow + k0 + a_k + 4);
            }
        }
        GEMM_MICRO(cur)
        if (has_next) {
            const int nxt = 1 - cur;
            As[nxt][a_k+0][a_row]=av0.x; As[nxt][a_k+1][a_row]=av0.y;
            As[nxt][a_k+2][a_row]=av0.z; As[nxt][a_k+3][a_row]=av0.w;
            As[nxt][a_k+4][a_row]=av1.x; As[nxt][a_k+5][a_row]=av1.y;
            As[nxt][a_k+6][a_row]=av1.z; As[nxt][a_k+7][a_row]=av1.w;
            Bs[nxt][a_k+0][t_l]=bv0.x; Bs[nxt][a_k+1][t_l]=bv0.y;
            Bs[nxt][a_k+2][t_l]=bv0.z; Bs[nxt][a_k+3][t_l]=bv0.w;
            Bs[nxt][a_k+4][t_l]=bv1.x; Bs[nxt][a_k+5][t_l]=bv1.y;
            Bs[nxt][a_k+6][t_l]=bv1.z; Bs[nxt][a_k+7][t_l]=bv1.w;
        }
        __syncthreads();
    }

    float lsum = 0.0f;
    #pragma unroll
    for (int half = 0; half < 2; half++) {
        #pragma unroll
        for (int i = 0; i < 4; i++) {
            const int m = half * 64 + ty * 4 + i;
            const int ai = half * 4 + i;
            #pragma unroll
            for (int jh = 0; jh < 2; jh++) {
                #pragma unroll
                for (int jj = 0; jj < 2; jj++) {
                    float2 v = unpack2(acc2[ai][jh * 2 + jj]);
                    const int t = col0 + jh * 64 + tx * 4 + jj * 2;
                    if (t < TTOK) {
                        const long li = (long)b * OUT_PER_B + (long)m * TTOK + t;
                        const float lg = 10.0f * tanhf(v.x * 0.0625f) + mask[li];
                        const float y = __expf(lg);
                        out[li] = y;
                        lsum += y;
                    }
                    if (t + 1 < TTOK) {
                        const long li = (long)b * OUT_PER_B + (long)m * TTOK + t + 1;
                        const float lg = 10.0f * tanhf(v.y * 0.0625f) + mask[li];
                        const float y = __expf(lg);
                        out[li] = y;
                        lsum += y;
                    }
                }
            }
        }
    }

    red[tid] = lsum;
    __syncthreads();
    #pragma unroll
    for (int s = 128; s > 0; s >>= 1) {
        if (tid < s) red[tid] += red[tid + s];
        __syncthreads();
    }
    if (tid == 0) atomicAdd(&sums[b], red[0]);
}

// =================== normalize: grid (chunks, batch) =======================
__global__ void __launch_bounds__(256)
norm_kernel(float4* __restrict__ out, const float* __restrict__ sums)
{
    const int b = blockIdx.y;
    const long per_b4 = OUT_PER_B / 4;     // 16416
    const long idx = (long)blockIdx.x * blockDim.x + threadIdx.x;
    if (idx < per_b4) {
        const float inv = 1.0f / sums[b];
        float4 v = out[(long)b * per_b4 + idx];
        v.x *= inv; v.y *= inv; v.z *= inv; v.w *= inv;
        out[(long)b * per_b4 + idx] = v;
    }
}

// =================== launch ===================
extern "C" void kernel_launch(void* const* d_in, const int* in_sizes, int n_in,
                              void* d_out, int out_size)
{
    const float* machine = (const float*)d_in[0];
    const float* jobs    = (const float*)d_in[1];
    const float* mask    = (const float*)d_in[2];
    const float* Wq3     = (const float*)d_in[3];
    const float* Wk      = (const float*)d_in[4];
    const float* Wv      = (const float*)d_in[5];
    const float* Wc      = (const float*)d_in[6];
    const float* bc      = (const float*)d_in[7];
    const float* skip    = (const float*)d_in[8];
    float* out = (float*)d_out;

    float *Qp, *Kp, *Vp, *Op, *MHp, *Sp;
    cudaGetSymbolAddress((void**)&Qp,  g_Q);
    cudaGetSymbolAddress((void**)&Kp,  g_K);
    cudaGetSymbolAddress((void**)&Vp,  g_V);
    cudaGetSymbolAddress((void**)&Op,  g_O);
    cudaGetSymbolAddress((void**)&MHp, g_MH);
    cudaGetSymbolAddress((void**)&Sp,  g_SUM);

    zero_sums_kernel<<<1, BATCH>>>(Sp);

    // Q + K + V projections in one launch (z selects)
    const int kv_tiles = (BATCH * TTOK + BM - 1) / BM;   // 257
    proj_kernel<<<dim3(EMBD / BN, kv_tiles, 3), 256>>>(
        jobs, skip, machine, Wk, Wv, Wq3, Kp, Vp, Qp);

    // attention
    attn_kernel<<<dim3(HEADS, BATCH), 128>>>(Qp, Kp, Vp, Op);

    // output projection + bias
    wc_kernel<<<dim3(EMBD / BN, (BATCH * MROWS) / BM), 256>>>(Op, Wc, bc, MHp);

    // score2 + clip + exp + per-batch sums
    score2_kernel<<<dim3((TTOK + BN - 1) / BN, 1, BATCH), 256>>>(
        MHp, jobs, skip, mask, out, Sp);

    // normalize
    const int per_b4 = OUT_PER_B / 4;      // 16416
    norm_kernel<<<dim3((per_b4 + 255) / 256, BATCH), 256>>>((float4*)out, Sp);
}